// round 5
// baseline (speedup 1.0000x reference)
#include <cuda_runtime.h>
#include <stdint.h>

#define HOPS 3
#define LBL  10
#define DIM  128
#define WPB  8                      // warps per block
#define THREADS (WPB * 32)
#define UNROLL 8
#define GRIDX 192                   // per hop; 3*192=576 blocks, 4/SM resident in one wave

// Scratch (__device__ globals — no allocation allowed)
__device__ float        g_sums[HOPS * LBL * DIM];
__device__ float        g_counts[LBL];
__device__ unsigned int g_done;

// ---------------------------------------------------------------------------
// Kernel 1: zero scratch + ticket. Tiny.
// ---------------------------------------------------------------------------
__global__ void init_kernel() {
    int i = blockIdx.x * blockDim.x + threadIdx.x;
    if (i < HOPS * LBL * DIM) g_sums[i] = 0.0f;
    if (i < LBL) g_counts[i] = 0.0f;
    if (i == 0) g_done = 0u;
}

// ---------------------------------------------------------------------------
// Main loop body, templated on label dtype (branch hoisted out of hot loop).
// One warp per node: 32 lanes read the 512B row as float4 (coalesced);
// label is warp-uniform -> conflict-free smem RMW into per-warp bank.
// ---------------------------------------------------------------------------
template <bool IS64>
__device__ __forceinline__ void hot_loop(const float4* __restrict__ e4,
                                         const void*   __restrict__ labels_raw,
                                         float* __restrict__ my,     // warp's acc bank
                                         int* __restrict__ mycnt,    // warp's count row (or null)
                                         int N, int gw, int nw, int lane) {
    const int*       l32 = reinterpret_cast<const int*>(labels_raw);
    const long long* l64 = reinterpret_cast<const long long*>(labels_raw);

    for (int base = gw * UNROLL; base < N; base += nw * UNROLL) {
        int    lab[UNROLL];
        float4 v[UNROLL];
#pragma unroll
        for (int k = 0; k < UNROLL; k++) {
            int n = base + k;
            if (n < N) {
                lab[k] = IS64 ? (int)l64[n] : l32[n];
                v[k]   = e4[(size_t)n * (DIM / 4) + lane];
            } else {
                lab[k] = -1;
            }
        }
#pragma unroll
        for (int k = 0; k < UNROLL; k++) {
            if (lab[k] >= 0) {
                float4* p = reinterpret_cast<float4*>(my + lab[k] * DIM + lane * 4);
                float4 cur = *p;
                cur.x += v[k].x; cur.y += v[k].y; cur.z += v[k].z; cur.w += v[k].w;
                *p = cur;
                if (mycnt && lane == 0) mycnt[lab[k]]++;   // warp-private, race-free
            }
        }
    }
}

// ---------------------------------------------------------------------------
// Kernel 2: accumulate + last-block finalize. blockIdx.y = hop.
// ---------------------------------------------------------------------------
__global__ void __launch_bounds__(THREADS, 4)
accumulate_kernel(const float* __restrict__ emb,
                  const void*  __restrict__ labels_raw,
                  int N,
                  const float* __restrict__ weight,
                  float* __restrict__ out,
                  int totalBlocks) {
    __shared__ __align__(16) float acc[WPB * LBL * DIM];  // 40 KB
    __shared__ int scnt[WPB][LBL];
    __shared__ int s_not64;
    __shared__ unsigned int s_ticket;

    const int tid  = threadIdx.x;
    const int warp = tid >> 5;
    const int lane = tid & 31;
    const int hop  = blockIdx.y;

    // --- zero smem + in-block labels dtype detection (overlapped) ---
    for (int i = tid; i < WPB * LBL * DIM; i += THREADS) acc[i] = 0.0f;
    if (tid < WPB * LBL) scnt[tid / LBL][tid % LBL] = 0;
    if (tid == 0) s_not64 = 0;
    __syncthreads();

    // int64 labels (values 0..9, LE) => all odd 32-bit words are 0.
    // int32 => P(first 4096 odd-index labels all zero) ~ 10^-4096.
    {
        const int* l32 = reinterpret_cast<const int*>(labels_raw);
        int nscan = N / 2; if (nscan > 4096) nscan = 4096;
        for (int j = tid; j < nscan; j += THREADS)
            if (l32[2 * j + 1] != 0) s_not64 = 1;
    }
    __syncthreads();
    const bool is64 = (s_not64 == 0);

    const float4* e4 = reinterpret_cast<const float4*>(emb) + (size_t)hop * N * (DIM / 4);
    float* my    = acc + warp * LBL * DIM;
    int*   mycnt = (hop == 0) ? scnt[warp] : nullptr;

    const int gw = blockIdx.x * WPB + warp;
    const int nw = gridDim.x * WPB;

    if (is64) hot_loop<true >(e4, labels_raw, my, mycnt, N, gw, nw, lane);
    else      hot_loop<false>(e4, labels_raw, my, mycnt, N, gw, nw, lane);
    __syncthreads();

    // --- block reduce 8 warp banks; one REDG per (label,dim) per block ---
    for (int i = tid; i < LBL * DIM; i += THREADS) {
        float s = 0.0f;
#pragma unroll
        for (int w = 0; w < WPB; w++) s += acc[w * LBL * DIM + i];
        atomicAdd(&g_sums[hop * LBL * DIM + i], s);
    }
    if (hop == 0 && tid < LBL) {
        int c = 0;
#pragma unroll
        for (int w = 0; w < WPB; w++) c += scnt[w][tid];
        if (c) atomicAdd(&g_counts[tid], (float)c);
    }

    // --- last-block ticket -> finalize ---
    __threadfence();
    if (tid == 0) s_ticket = atomicAdd(&g_done, 1u);
    __syncthreads();
    if (s_ticket == (unsigned int)(totalBlocks - 1)) {
        for (int i = tid; i < HOPS * LBL * DIM; i += THREADS) {
            int l = (i / DIM) % LBL;
            float c = __ldcg(&g_counts[l]);
            if (c < 1.0f) c = 1.0f;
            out[i] = __ldcg(&g_sums[i]) / c + weight[i];
        }
        if (tid < LBL)
            out[HOPS * LBL * DIM + tid] = __ldcg(&g_counts[tid]);
    }
}

// ---------------------------------------------------------------------------
extern "C" void kernel_launch(void* const* d_in, const int* in_sizes, int n_in,
                              void* d_out, int out_size) {
    const float* emb    = (const float*)d_in[0];   // [3, N, 128] f32
    const void*  labels = d_in[1];                 // [N] int32 or int64
    const float* weight = (const float*)d_in[2];   // [3, 10, 128] f32
    float*       out    = (float*)d_out;           // 3850 f32

    const int N = in_sizes[1];

    init_kernel<<<(HOPS * LBL * DIM + 255) / 256, 256>>>();

    dim3 grid(GRIDX, HOPS, 1);
    accumulate_kernel<<<grid, THREADS>>>(emb, labels, N, weight, out,
                                         GRIDX * HOPS);
}